// round 3
// baseline (speedup 1.0000x reference)
#include <cuda_runtime.h>
#include <cuda_fp16.h>

// ContrastHead: neighbor-contrastive loss.
//   N=200000 points, K=16 neighbors, C=32 features, T=0.1, weight=0.1, eps=1e-8
// Inputs: features f32 [N*C], labels i32 [N], neighbor_idx [N*K] (int32/int64 runtime-detect)
// Output: 1 float.
//
// R3: lane-per-neighbor (2 points/warp, MLP~8), fp16 feature table (64B rows),
// uint8 label table (200KB -> L1-resident), per-block partials, 1-block finalize.

#define KNB 16
#define CF  32
#define NMAX 200064
#define MAXBLK 32768

__device__ __align__(16) uint4 g_feat16[NMAX * 4];     // N rows x 32 halfs = 4 uint4/row
__device__ __align__(4) unsigned char g_lab8[NMAX];    // labels < 17 fit in u8
__device__ float2 g_part[MAXBLK];

// One streaming pass: features f32->f16 (4 threads/row) + labels i32->u8 (4 labels/thread).
__global__ __launch_bounds__(256) void ch_convert_kernel(
    const float4* __restrict__ feat, const int* __restrict__ labels, int n)
{
    const int tot8 = n * 4;               // 8 floats per thread
    const int labw = (n + 3) >> 2;        // 4 labels per thread
    const int i = blockIdx.x * blockDim.x + threadIdx.x;
    if (i < tot8) {
        float4 a = feat[2 * i];
        float4 b = feat[2 * i + 1];
        __half2 h0 = __floats2half2_rn(a.x, a.y);
        __half2 h1 = __floats2half2_rn(a.z, a.w);
        __half2 h2 = __floats2half2_rn(b.x, b.y);
        __half2 h3 = __floats2half2_rn(b.z, b.w);
        uint4 o;
        o.x = *reinterpret_cast<unsigned*>(&h0);
        o.y = *reinterpret_cast<unsigned*>(&h1);
        o.z = *reinterpret_cast<unsigned*>(&h2);
        o.w = *reinterpret_cast<unsigned*>(&h3);
        g_feat16[i] = o;
    } else if (i < tot8 + labw) {
        const int k = i - tot8;
        const int base = 4 * k;
        uchar4 o;
        o.x = (unsigned char)labels[base];
        o.y = (unsigned char)labels[(base + 1 < n) ? base + 1 : n - 1];
        o.z = (unsigned char)labels[(base + 2 < n) ? base + 2 : n - 1];
        o.w = (unsigned char)labels[(base + 3 < n) ? base + 3 : n - 1];
        reinterpret_cast<uchar4*>(g_lab8)[k] = o;
    }
}

__device__ __forceinline__ float dist8(uint4 c, uint4 nf) {
    float sum = 0.0f;
    const __half2* ch = reinterpret_cast<const __half2*>(&c);
    const __half2* nh = reinterpret_cast<const __half2*>(&nf);
#pragma unroll
    for (int q = 0; q < 4; q++) {
        float2 fc = __half22float2(ch[q]);
        float2 fn = __half22float2(nh[q]);
        float d0 = fc.x - fn.x;
        float d1 = fc.y - fn.y;
        sum = fmaf(d0, d0, sum);
        sum = fmaf(d1, d1, sum);
    }
    return sum;
}

// 2 points per warp: lanes 0..15 -> neighbors of point 2w, lanes 16..31 -> point 2w+1.
__global__ __launch_bounds__(256) void ch_main_kernel(
    const void* __restrict__ nbr, int n)
{
    const unsigned FULL = 0xffffffffu;
    const int lane = threadIdx.x & 31;
    const int wid  = threadIdx.x >> 5;
    const int w    = (blockIdx.x * blockDim.x + threadIdx.x) >> 5;
    const int half = lane >> 4;
    const int j    = lane & 15;
    const int p    = 2 * w + half;
    const bool active = (p < n);
    const int pc = active ? p : 0;

    // dtype detect: int64 -> odd 32-bit words of first 16 entries all zero.
    int probe = 1;
    if (lane < 16) probe = reinterpret_cast<const int*>(nbr)[2 * lane + 1];
    const bool is64 = ((__ballot_sync(FULL, probe == 0) & 0xFFFFu) == 0xFFFFu);

    int idx;
    if (is64)
        idx = (int)reinterpret_cast<const long long*>(nbr)[(size_t)pc * KNB + j];
    else
        idx = reinterpret_cast<const int*>(nbr)[(size_t)pc * KNB + j];

    const int lab   = g_lab8[pc];     // broadcast within half (L1)
    const int nblab = g_lab8[idx];    // random 1B load, 200KB table ~ L1-resident

    // center row (broadcast within half) + neighbor row (4 independent 16B loads)
    const uint4* fp = g_feat16;
    const size_t cb = (size_t)pc * 4;
    const size_t nb = (size_t)idx * 4;
    const uint4 c0 = fp[cb + 0], c1 = fp[cb + 1], c2 = fp[cb + 2], c3 = fp[cb + 3];
    const uint4 n0 = fp[nb + 0], n1 = fp[nb + 1], n2 = fp[nb + 2], n3 = fp[nb + 3];

    const float d2 = dist8(c0, n0) + dist8(c1, n1) + dist8(c2, n2) + dist8(c3, n3);
    const float nd = -sqrtf(d2 + 1e-8f);

    // softmax over the 16 lanes of this half (xor<16 never crosses halves)
    float m = nd;
    m = fmaxf(m, __shfl_xor_sync(FULL, m, 8));
    m = fmaxf(m, __shfl_xor_sync(FULL, m, 4));
    m = fmaxf(m, __shfl_xor_sync(FULL, m, 2));
    m = fmaxf(m, __shfl_xor_sync(FULL, m, 1));

    const float e = __expf((nd - m) * 10.0f);    // 1/T = 10
    const bool ispos = (nblab == lab);
    float pos = ispos ? e : 0.0f;
    float neg = e;
#pragma unroll
    for (int off = 8; off >= 1; off >>= 1) {
        pos += __shfl_xor_sync(FULL, pos, off);
        neg += __shfl_xor_sync(FULL, neg, off);
    }
    const unsigned bal = __ballot_sync(FULL, ispos);
    const int cnt = __popc(bal & (half ? 0xFFFF0000u : 0x0000FFFFu));

    __shared__ float s_num[16];
    __shared__ float s_den[16];
    if (j == 0) {
        const float pm = (active && cnt > 0 && cnt < KNB) ? 1.0f : 0.0f;
        const float loss = -__logf(pos / neg + 1e-8f);
        s_num[wid * 2 + half] = loss * pm;
        s_den[wid * 2 + half] = pm;
    }
    __syncthreads();
    if (threadIdx.x == 0) {
        float a = 0.0f, b = 0.0f;
#pragma unroll
        for (int i = 0; i < 16; i++) { a += s_num[i]; b += s_den[i]; }
        g_part[blockIdx.x] = make_float2(a, b);
    }
}

__global__ __launch_bounds__(1024) void ch_finalize_kernel(
    float* __restrict__ out, int nblocks)
{
    const unsigned FULL = 0xffffffffu;
    float a = 0.0f, b = 0.0f;
    for (int i = threadIdx.x; i < nblocks; i += 1024) {
        float2 v = g_part[i];
        a += v.x; b += v.y;
    }
#pragma unroll
    for (int off = 16; off >= 1; off >>= 1) {
        a += __shfl_xor_sync(FULL, a, off);
        b += __shfl_xor_sync(FULL, b, off);
    }
    __shared__ float sa[32], sb[32];
    if ((threadIdx.x & 31) == 0) { sa[threadIdx.x >> 5] = a; sb[threadIdx.x >> 5] = b; }
    __syncthreads();
    if (threadIdx.x == 0) {
        double na = 0.0, nb = 0.0;
#pragma unroll
        for (int i = 0; i < 32; i++) { na += sa[i]; nb += sb[i]; }
        if (nb < 1.0) nb = 1.0;
        out[0] = (float)(na / nb * 0.1);   // WEIGHT = 0.1
    }
}

extern "C" void kernel_launch(void* const* d_in, const int* in_sizes, int n_in,
                              void* d_out, int out_size) {
    const float* feat   = (const float*)d_in[0];
    const int*   labels = (const int*)d_in[1];
    const void*  nbr    = (const void*)d_in[2];
    float* out = (float*)d_out;
    (void)n_in; (void)out_size;

    const int n = in_sizes[1];                 // N points
    const int work = n * 4 + ((n + 3) >> 2);   // feature chunks + label packs
    ch_convert_kernel<<<(work + 255) / 256, 256>>>((const float4*)feat, labels, n);

    const int blocks = (n + 15) / 16;          // 16 points per block (8 warps x 2)
    ch_main_kernel<<<blocks, 256>>>(nbr, n);

    ch_finalize_kernel<<<1, 1024>>>(out, blocks);
}